// round 3
// baseline (speedup 1.0000x reference)
#include <cuda_runtime.h>
#include <math_constants.h>

// Problem constants
constexpr int Bc = 4;
constexpr int Nn = 1024;
constexpr int Cc = 1024;
constexpr int Hh = 16;
constexpr int Dd = 64;          // head dim
constexpr int BH = Bc * Hh;     // 64
constexpr int M1 = Bc * Nn;     // 4096 rows of x
constexpr int NQKV = 3 * Cc;    // 3072

constexpr size_t QKV_ELEMS = (size_t)BH * Nn * Dd;   // 4,194,304 per tensor
constexpr size_t OUT_ELEMS = (size_t)Bc * Nn * Cc;   // 4,194,304
constexpr size_t ATTN_ELEMS = (size_t)BH * Nn * Nn;  // 67,108,864

// Scratch (device globals — no allocations allowed)
__device__ float g_q[QKV_ELEMS];
__device__ float g_k[QKV_ELEMS];
__device__ float g_v[QKV_ELEMS];
__device__ float g_oh[OUT_ELEMS];   // merged heads [B, N, C]

// ---------------------------------------------------------------------------
// Kernel 1: QKV GEMM.  X[4096,1024] @ W[1024,3072] + b -> scatter into Q,K,V
// laid out [BH, N, HD].  128x128 tile, BK=8, 256 threads, 8x8 microtile.
// ---------------------------------------------------------------------------
__global__ __launch_bounds__(256) void qkv_gemm(const float* __restrict__ X,
                                                const float* __restrict__ W,
                                                const float* __restrict__ bias)
{
    __shared__ float As[8][128];
    __shared__ float Bs[8][128];
    const int tid = threadIdx.x;
    const int m0 = blockIdx.y * 128;
    const int n0 = blockIdx.x * 128;
    const int tx = tid & 15, ty = tid >> 4;

    const int arow = tid >> 1, acol = (tid & 1) * 4;
    const int brow = tid >> 5, bcol = (tid & 31) * 4;

    float acc[8][8];
#pragma unroll
    for (int i = 0; i < 8; i++)
#pragma unroll
        for (int j = 0; j < 8; j++) acc[i][j] = 0.0f;

    for (int k0 = 0; k0 < Cc; k0 += 8) {
        float4 av = *(const float4*)(X + (size_t)(m0 + arow) * Cc + k0 + acol);
        As[acol + 0][arow] = av.x;
        As[acol + 1][arow] = av.y;
        As[acol + 2][arow] = av.z;
        As[acol + 3][arow] = av.w;
        float4 bv = *(const float4*)(W + (size_t)(k0 + brow) * NQKV + n0 + bcol);
        *(float4*)&Bs[brow][bcol] = bv;
        __syncthreads();
#pragma unroll
        for (int k = 0; k < 8; k++) {
            float ra[8], rb[8];
            *(float4*)&ra[0] = *(const float4*)&As[k][ty * 8];
            *(float4*)&ra[4] = *(const float4*)&As[k][ty * 8 + 4];
            *(float4*)&rb[0] = *(const float4*)&Bs[k][tx * 8];
            *(float4*)&rb[4] = *(const float4*)&Bs[k][tx * 8 + 4];
#pragma unroll
            for (int i = 0; i < 8; i++)
#pragma unroll
                for (int j = 0; j < 8; j++) acc[i][j] = fmaf(ra[i], rb[j], acc[i][j]);
        }
        __syncthreads();
    }

#pragma unroll
    for (int i = 0; i < 8; i++) {
        const int m = m0 + ty * 8 + i;
        const int b = m >> 10, nn = m & 1023;
#pragma unroll
        for (int j = 0; j < 8; j++) {
            const int n = n0 + tx * 8 + j;
            float v = acc[i][j] + bias[n];
            const int part = n >> 10;
            const int w = n & 1023;
            const int h = w >> 6, d = w & 63;
            const size_t idx = (((size_t)(b * Hh + h)) * Nn + nn) * Dd + d;
            if (part == 0)       g_q[idx] = v * 0.125f;   // HD^-0.5
            else if (part == 1)  g_k[idx] = v;
            else                 g_v[idx] = v;
        }
    }
}

// ---------------------------------------------------------------------------
// Kernel 2: logits = Q @ K^T + int_matrix + (1-mask)*-1e9 -> attn buffer.
// Per (b,h): [1024,64]@[64,1024].  64x64 tile, full K=64 in smem.
// ---------------------------------------------------------------------------
__global__ __launch_bounds__(256) void qk_logits(const float* __restrict__ IM,
                                                 const float* __restrict__ MASK,
                                                 float* __restrict__ attn)
{
    const int z = blockIdx.z;                 // b*H + h
    const int r0 = blockIdx.y * 64;
    const int c0 = blockIdx.x * 64;
    __shared__ float Qs[64][65];
    __shared__ float Ks[64][65];
    const float* Qb = g_q + (size_t)z * Nn * Dd;
    const float* Kb = g_k + (size_t)z * Nn * Dd;
    const int tid = threadIdx.x;

    for (int i = tid; i < 64 * 64; i += 256) {
        const int r = i >> 6, c = i & 63;
        Qs[r][c] = Qb[(size_t)(r0 + r) * Dd + c];
        Ks[r][c] = Kb[(size_t)(c0 + r) * Dd + c];
    }
    __syncthreads();

    const int tx = tid & 15, ty = tid >> 4;
    float acc[4][4];
#pragma unroll
    for (int i = 0; i < 4; i++)
#pragma unroll
        for (int j = 0; j < 4; j++) acc[i][j] = 0.0f;

#pragma unroll 8
    for (int k = 0; k < 64; k++) {
        float a[4], bb[4];
#pragma unroll
        for (int i = 0; i < 4; i++) a[i] = Qs[ty * 4 + i][k];
#pragma unroll
        for (int j = 0; j < 4; j++) bb[j] = Ks[tx * 4 + j][k];
#pragma unroll
        for (int i = 0; i < 4; i++)
#pragma unroll
            for (int j = 0; j < 4; j++) acc[i][j] = fmaf(a[i], bb[j], acc[i][j]);
    }

    const int b = z >> 4;
    const float* imz = IM + (size_t)z * Nn * Nn;
    const float* mkb = MASK + (size_t)b * Nn * Nn;
    float* az = attn + (size_t)z * Nn * Nn;
#pragma unroll
    for (int i = 0; i < 4; i++) {
        const int r = r0 + ty * 4 + i;
#pragma unroll
        for (int j = 0; j < 4; j++) {
            const int c = c0 + tx * 4 + j;
            const size_t off = (size_t)r * Nn + c;
            az[off] = acc[i][j] + imz[off] + (1.0f - mkb[off]) * -1e9f;
        }
    }
}

// ---------------------------------------------------------------------------
// Kernel 3: row softmax over 1024 elements, in place.  One block per row.
// ---------------------------------------------------------------------------
__device__ __forceinline__ float warpMax(float v) {
#pragma unroll
    for (int o = 16; o; o >>= 1) v = fmaxf(v, __shfl_xor_sync(0xffffffffu, v, o));
    return v;
}
__device__ __forceinline__ float warpSum(float v) {
#pragma unroll
    for (int o = 16; o; o >>= 1) v += __shfl_xor_sync(0xffffffffu, v, o);
    return v;
}

__global__ __launch_bounds__(256) void softmax_rows(float* __restrict__ attn)
{
    __shared__ float sm[8];
    __shared__ float ss[8];
    const size_t row = blockIdx.x;
    float4* p = (float4*)(attn + row * Nn);
    const int tid = threadIdx.x;
    const int lane = tid & 31, wid = tid >> 5;

    float4 v = p[tid];
    float m = fmaxf(fmaxf(v.x, v.y), fmaxf(v.z, v.w));
    m = warpMax(m);
    if (lane == 0) sm[wid] = m;
    __syncthreads();
    if (tid < 32) {
        float t = (tid < 8) ? sm[tid] : -CUDART_INF_F;
        t = warpMax(t);
        if (tid == 0) sm[0] = t;
    }
    __syncthreads();
    m = sm[0];

    float4 e;
    e.x = expf(v.x - m);
    e.y = expf(v.y - m);
    e.z = expf(v.z - m);
    e.w = expf(v.w - m);
    float s = e.x + e.y + e.z + e.w;
    s = warpSum(s);
    if (lane == 0) ss[wid] = s;
    __syncthreads();
    if (tid < 32) {
        float t = (tid < 8) ? ss[tid] : 0.0f;
        t = warpSum(t);
        if (tid == 0) ss[0] = t;
    }
    __syncthreads();
    const float inv = 1.0f / ss[0];
    e.x *= inv; e.y *= inv; e.z *= inv; e.w *= inv;
    p[tid] = e;
}

// ---------------------------------------------------------------------------
// Kernel 4: out_heads = attn @ V.  Per (b,h): [1024,1024]@[1024,64].
// 64 rows x 64 cols (full Dd) per block, BK=64.
// ---------------------------------------------------------------------------
__global__ __launch_bounds__(256) void av_gemm(const float* __restrict__ attn)
{
    const int z = blockIdx.y;
    const int r0 = blockIdx.x * 64;
    __shared__ float As[64][65];
    __shared__ float Vs[64][65];
    const float* Ab = attn + (size_t)z * Nn * Nn;
    const float* Vb = g_v + (size_t)z * Nn * Dd;
    const int tid = threadIdx.x;
    const int tx = tid & 15, ty = tid >> 4;

    float acc[4][4];
#pragma unroll
    for (int i = 0; i < 4; i++)
#pragma unroll
        for (int j = 0; j < 4; j++) acc[i][j] = 0.0f;

    for (int k0 = 0; k0 < Nn; k0 += 64) {
        for (int i = tid; i < 64 * 64; i += 256) {
            const int r = i >> 6, c = i & 63;
            As[r][c] = Ab[(size_t)(r0 + r) * Nn + k0 + c];
            Vs[r][c] = Vb[(size_t)(k0 + r) * Dd + c];
        }
        __syncthreads();
#pragma unroll 8
        for (int k = 0; k < 64; k++) {
            float a[4], bb[4];
#pragma unroll
            for (int i = 0; i < 4; i++) a[i] = As[ty * 4 + i][k];
#pragma unroll
            for (int j = 0; j < 4; j++) bb[j] = Vs[k][tx * 4 + j];
#pragma unroll
            for (int i = 0; i < 4; i++)
#pragma unroll
                for (int j = 0; j < 4; j++) acc[i][j] = fmaf(a[i], bb[j], acc[i][j]);
        }
        __syncthreads();
    }

    const int b = z >> 4, h = z & 15;
#pragma unroll
    for (int i = 0; i < 4; i++) {
        const int r = r0 + ty * 4 + i;
#pragma unroll
        for (int j = 0; j < 4; j++) {
            const int d = tx * 4 + j;
            g_oh[((size_t)b * Nn + r) * Cc + h * Dd + d] = acc[i][j];
        }
    }
}

// ---------------------------------------------------------------------------
// Kernel 5: final projection.  OH[4096,1024] @ Wp[1024,1024] + bp -> out.
// Same structure as kernel 1.
// ---------------------------------------------------------------------------
__global__ __launch_bounds__(256) void proj_gemm(const float* __restrict__ Wp,
                                                 const float* __restrict__ bp,
                                                 float* __restrict__ out)
{
    __shared__ float As[8][128];
    __shared__ float Bs[8][128];
    const int tid = threadIdx.x;
    const int m0 = blockIdx.y * 128;
    const int n0 = blockIdx.x * 128;
    const int tx = tid & 15, ty = tid >> 4;

    const int arow = tid >> 1, acol = (tid & 1) * 4;
    const int brow = tid >> 5, bcol = (tid & 31) * 4;

    float acc[8][8];
#pragma unroll
    for (int i = 0; i < 8; i++)
#pragma unroll
        for (int j = 0; j < 8; j++) acc[i][j] = 0.0f;

    for (int k0 = 0; k0 < Cc; k0 += 8) {
        float4 av = *(const float4*)(g_oh + (size_t)(m0 + arow) * Cc + k0 + acol);
        As[acol + 0][arow] = av.x;
        As[acol + 1][arow] = av.y;
        As[acol + 2][arow] = av.z;
        As[acol + 3][arow] = av.w;
        float4 bv = *(const float4*)(Wp + (size_t)(k0 + brow) * Cc + n0 + bcol);
        *(float4*)&Bs[brow][bcol] = bv;
        __syncthreads();
#pragma unroll
        for (int k = 0; k < 8; k++) {
            float ra[8], rb[8];
            *(float4*)&ra[0] = *(const float4*)&As[k][ty * 8];
            *(float4*)&ra[4] = *(const float4*)&As[k][ty * 8 + 4];
            *(float4*)&rb[0] = *(const float4*)&Bs[k][tx * 8];
            *(float4*)&rb[4] = *(const float4*)&Bs[k][tx * 8 + 4];
#pragma unroll
            for (int i = 0; i < 8; i++)
#pragma unroll
                for (int j = 0; j < 8; j++) acc[i][j] = fmaf(ra[i], rb[j], acc[i][j]);
        }
        __syncthreads();
    }

#pragma unroll
    for (int i = 0; i < 8; i++) {
        const int m = m0 + ty * 8 + i;
#pragma unroll
        for (int j = 0; j < 8; j++) {
            const int n = n0 + tx * 8 + j;
            out[(size_t)m * Cc + n] = acc[i][j] + bp[n];
        }
    }
}

// ---------------------------------------------------------------------------
extern "C" void kernel_launch(void* const* d_in, const int* in_sizes, int n_in,
                              void* d_out, int out_size)
{
    const float* x     = (const float*)d_in[0];  // [B,N,C]
    const float* im    = (const float*)d_in[1];  // [B,H,N,N]
    const float* mask  = (const float*)d_in[2];  // [B,1,N,N]
    const float* Wqkv  = (const float*)d_in[3];  // [C,3C]
    const float* bqkv  = (const float*)d_in[4];  // [3C]
    const float* Wproj = (const float*)d_in[5];  // [C,C]
    const float* bproj = (const float*)d_in[6];  // [C]

    float* out  = (float*)d_out;                 // [B,N,C]
    float* attn = out + OUT_ELEMS;               // [B,H,N,N]

    (void)in_sizes; (void)n_in; (void)out_size;

    qkv_gemm<<<dim3(NQKV / 128, M1 / 128), 256>>>(x, Wqkv, bqkv);
    qk_logits<<<dim3(Nn / 64, Nn / 64, BH), 256>>>(im, mask, attn);
    softmax_rows<<<(unsigned)(BH * Nn), 256>>>(attn);
    av_gemm<<<dim3(Nn / 64, BH), 256>>>(attn);
    proj_gemm<<<dim3(Cc / 128, M1 / 128), 256>>>(Wproj, bproj, out);
}

// round 4
// speedup vs baseline: 1.0029x; 1.0029x over previous
#include <cuda_runtime.h>
#include <math_constants.h>

// Problem constants
constexpr int Bc = 4;
constexpr int Nn = 1024;
constexpr int Cc = 1024;
constexpr int Hh = 16;
constexpr int Dd = 64;          // head dim
constexpr int BH = Bc * Hh;     // 64
constexpr int M1 = Bc * Nn;     // 4096 rows of x
constexpr int NQKV = 3 * Cc;    // 3072

constexpr size_t QKV_ELEMS = (size_t)BH * Nn * Dd;   // 4,194,304 per tensor
constexpr size_t OUT_ELEMS = (size_t)Bc * Nn * Cc;   // 4,194,304
constexpr size_t ATTN_ELEMS = (size_t)BH * Nn * Nn;  // 67,108,864

// Scratch (device globals — no allocations allowed)
__device__ float g_q[QKV_ELEMS];
__device__ float g_k[QKV_ELEMS];
__device__ float g_v[QKV_ELEMS];
__device__ float g_oh[OUT_ELEMS];   // merged heads [B, N, C]

// ---------------------------------------------------------------------------
// Kernel 1: QKV GEMM.  X[4096,1024] @ W[1024,3072] + b -> scatter into Q,K,V
// laid out [BH, N, HD].  128x128 tile, BK=8, 256 threads, 8x8 microtile.
// ---------------------------------------------------------------------------
__global__ __launch_bounds__(256) void qkv_gemm(const float* __restrict__ X,
                                                const float* __restrict__ W,
                                                const float* __restrict__ bias)
{
    __shared__ float As[8][128];
    __shared__ float Bs[8][128];
    const int tid = threadIdx.x;
    const int m0 = blockIdx.y * 128;
    const int n0 = blockIdx.x * 128;
    const int tx = tid & 15, ty = tid >> 4;

    const int arow = tid >> 1, acol = (tid & 1) * 4;
    const int brow = tid >> 5, bcol = (tid & 31) * 4;

    float acc[8][8];
#pragma unroll
    for (int i = 0; i < 8; i++)
#pragma unroll
        for (int j = 0; j < 8; j++) acc[i][j] = 0.0f;

    for (int k0 = 0; k0 < Cc; k0 += 8) {
        float4 av = *(const float4*)(X + (size_t)(m0 + arow) * Cc + k0 + acol);
        As[acol + 0][arow] = av.x;
        As[acol + 1][arow] = av.y;
        As[acol + 2][arow] = av.z;
        As[acol + 3][arow] = av.w;
        float4 bv = *(const float4*)(W + (size_t)(k0 + brow) * NQKV + n0 + bcol);
        *(float4*)&Bs[brow][bcol] = bv;
        __syncthreads();
#pragma unroll
        for (int k = 0; k < 8; k++) {
            float ra[8], rb[8];
            *(float4*)&ra[0] = *(const float4*)&As[k][ty * 8];
            *(float4*)&ra[4] = *(const float4*)&As[k][ty * 8 + 4];
            *(float4*)&rb[0] = *(const float4*)&Bs[k][tx * 8];
            *(float4*)&rb[4] = *(const float4*)&Bs[k][tx * 8 + 4];
#pragma unroll
            for (int i = 0; i < 8; i++)
#pragma unroll
                for (int j = 0; j < 8; j++) acc[i][j] = fmaf(ra[i], rb[j], acc[i][j]);
        }
        __syncthreads();
    }

#pragma unroll
    for (int i = 0; i < 8; i++) {
        const int m = m0 + ty * 8 + i;
        const int b = m >> 10, nn = m & 1023;
#pragma unroll
        for (int j = 0; j < 8; j++) {
            const int n = n0 + tx * 8 + j;
            float v = acc[i][j] + bias[n];
            const int part = n >> 10;
            const int w = n & 1023;
            const int h = w >> 6, d = w & 63;
            const size_t idx = (((size_t)(b * Hh + h)) * Nn + nn) * Dd + d;
            if (part == 0)       g_q[idx] = v * 0.125f;   // HD^-0.5
            else if (part == 1)  g_k[idx] = v;
            else                 g_v[idx] = v;
        }
    }
}

// ---------------------------------------------------------------------------
// Kernel 2: logits = Q @ K^T + int_matrix + (1-mask)*-1e9 -> attn buffer.
// Per (b,h): [1024,64]@[64,1024].  64x64 tile, full K=64 in smem.
// ---------------------------------------------------------------------------
__global__ __launch_bounds__(256) void qk_logits(const float* __restrict__ IM,
                                                 const float* __restrict__ MASK,
                                                 float* __restrict__ attn)
{
    const int z = blockIdx.z;                 // b*H + h
    const int r0 = blockIdx.y * 64;
    const int c0 = blockIdx.x * 64;
    __shared__ float Qs[64][65];
    __shared__ float Ks[64][65];
    const float* Qb = g_q + (size_t)z * Nn * Dd;
    const float* Kb = g_k + (size_t)z * Nn * Dd;
    const int tid = threadIdx.x;

    for (int i = tid; i < 64 * 64; i += 256) {
        const int r = i >> 6, c = i & 63;
        Qs[r][c] = Qb[(size_t)(r0 + r) * Dd + c];
        Ks[r][c] = Kb[(size_t)(c0 + r) * Dd + c];
    }
    __syncthreads();

    const int tx = tid & 15, ty = tid >> 4;
    float acc[4][4];
#pragma unroll
    for (int i = 0; i < 4; i++)
#pragma unroll
        for (int j = 0; j < 4; j++) acc[i][j] = 0.0f;

#pragma unroll 8
    for (int k = 0; k < 64; k++) {
        float a[4], bb[4];
#pragma unroll
        for (int i = 0; i < 4; i++) a[i] = Qs[ty * 4 + i][k];
#pragma unroll
        for (int j = 0; j < 4; j++) bb[j] = Ks[tx * 4 + j][k];
#pragma unroll
        for (int i = 0; i < 4; i++)
#pragma unroll
            for (int j = 0; j < 4; j++) acc[i][j] = fmaf(a[i], bb[j], acc[i][j]);
    }

    const int b = z >> 4;
    const float* imz = IM + (size_t)z * Nn * Nn;
    const float* mkb = MASK + (size_t)b * Nn * Nn;
    float* az = attn + (size_t)z * Nn * Nn;
#pragma unroll
    for (int i = 0; i < 4; i++) {
        const int r = r0 + ty * 4 + i;
#pragma unroll
        for (int j = 0; j < 4; j++) {
            const int c = c0 + tx * 4 + j;
            const size_t off = (size_t)r * Nn + c;
            az[off] = acc[i][j] + imz[off] + (1.0f - mkb[off]) * -1e9f;
        }
    }
}

// ---------------------------------------------------------------------------
// Kernel 3: row softmax over 1024 elements, in place.  One block per row.
// ---------------------------------------------------------------------------
__device__ __forceinline__ float warpMax(float v) {
#pragma unroll
    for (int o = 16; o; o >>= 1) v = fmaxf(v, __shfl_xor_sync(0xffffffffu, v, o));
    return v;
}
__device__ __forceinline__ float warpSum(float v) {
#pragma unroll
    for (int o = 16; o; o >>= 1) v += __shfl_xor_sync(0xffffffffu, v, o);
    return v;
}

__global__ __launch_bounds__(256) void softmax_rows(float* __restrict__ attn)
{
    __shared__ float sm[8];
    __shared__ float ss[8];
    const size_t row = blockIdx.x;
    float4* p = (float4*)(attn + row * Nn);
    const int tid = threadIdx.x;
    const int lane = tid & 31, wid = tid >> 5;

    float4 v = p[tid];
    float m = fmaxf(fmaxf(v.x, v.y), fmaxf(v.z, v.w));
    m = warpMax(m);
    if (lane == 0) sm[wid] = m;
    __syncthreads();
    if (tid < 32) {
        float t = (tid < 8) ? sm[tid] : -CUDART_INF_F;
        t = warpMax(t);
        if (tid == 0) sm[0] = t;
    }
    __syncthreads();
    m = sm[0];

    float4 e;
    e.x = expf(v.x - m);
    e.y = expf(v.y - m);
    e.z = expf(v.z - m);
    e.w = expf(v.w - m);
    float s = e.x + e.y + e.z + e.w;
    s = warpSum(s);
    if (lane == 0) ss[wid] = s;
    __syncthreads();
    if (tid < 32) {
        float t = (tid < 8) ? ss[tid] : 0.0f;
        t = warpSum(t);
        if (tid == 0) ss[0] = t;
    }
    __syncthreads();
    const float inv = 1.0f / ss[0];
    e.x *= inv; e.y *= inv; e.z *= inv; e.w *= inv;
    p[tid] = e;
}

// ---------------------------------------------------------------------------
// Kernel 4: out_heads = attn @ V.  Per (b,h): [1024,1024]@[1024,64].
// 64 rows x 64 cols (full Dd) per block, BK=64.
// ---------------------------------------------------------------------------
__global__ __launch_bounds__(256) void av_gemm(const float* __restrict__ attn)
{
    const int z = blockIdx.y;
    const int r0 = blockIdx.x * 64;
    __shared__ float As[64][65];
    __shared__ float Vs[64][65];
    const float* Ab = attn + (size_t)z * Nn * Nn;
    const float* Vb = g_v + (size_t)z * Nn * Dd;
    const int tid = threadIdx.x;
    const int tx = tid & 15, ty = tid >> 4;

    float acc[4][4];
#pragma unroll
    for (int i = 0; i < 4; i++)
#pragma unroll
        for (int j = 0; j < 4; j++) acc[i][j] = 0.0f;

    for (int k0 = 0; k0 < Nn; k0 += 64) {
        for (int i = tid; i < 64 * 64; i += 256) {
            const int r = i >> 6, c = i & 63;
            As[r][c] = Ab[(size_t)(r0 + r) * Nn + k0 + c];
            Vs[r][c] = Vb[(size_t)(k0 + r) * Dd + c];
        }
        __syncthreads();
#pragma unroll 8
        for (int k = 0; k < 64; k++) {
            float a[4], bb[4];
#pragma unroll
            for (int i = 0; i < 4; i++) a[i] = As[ty * 4 + i][k];
#pragma unroll
            for (int j = 0; j < 4; j++) bb[j] = Vs[k][tx * 4 + j];
#pragma unroll
            for (int i = 0; i < 4; i++)
#pragma unroll
                for (int j = 0; j < 4; j++) acc[i][j] = fmaf(a[i], bb[j], acc[i][j]);
        }
        __syncthreads();
    }

    const int b = z >> 4, h = z & 15;
#pragma unroll
    for (int i = 0; i < 4; i++) {
        const int r = r0 + ty * 4 + i;
#pragma unroll
        for (int j = 0; j < 4; j++) {
            const int d = tx * 4 + j;
            g_oh[((size_t)b * Nn + r) * Cc + h * Dd + d] = acc[i][j];
        }
    }
}

// ---------------------------------------------------------------------------
// Kernel 5: final projection.  OH[4096,1024] @ Wp[1024,1024] + bp -> out.
// Same structure as kernel 1.
// ---------------------------------------------------------------------------
__global__ __launch_bounds__(256) void proj_gemm(const float* __restrict__ Wp,
                                                 const float* __restrict__ bp,
                                                 float* __restrict__ out)
{
    __shared__ float As[8][128];
    __shared__ float Bs[8][128];
    const int tid = threadIdx.x;
    const int m0 = blockIdx.y * 128;
    const int n0 = blockIdx.x * 128;
    const int tx = tid & 15, ty = tid >> 4;

    const int arow = tid >> 1, acol = (tid & 1) * 4;
    const int brow = tid >> 5, bcol = (tid & 31) * 4;

    float acc[8][8];
#pragma unroll
    for (int i = 0; i < 8; i++)
#pragma unroll
        for (int j = 0; j < 8; j++) acc[i][j] = 0.0f;

    for (int k0 = 0; k0 < Cc; k0 += 8) {
        float4 av = *(const float4*)(g_oh + (size_t)(m0 + arow) * Cc + k0 + acol);
        As[acol + 0][arow] = av.x;
        As[acol + 1][arow] = av.y;
        As[acol + 2][arow] = av.z;
        As[acol + 3][arow] = av.w;
        float4 bv = *(const float4*)(Wp + (size_t)(k0 + brow) * Cc + n0 + bcol);
        *(float4*)&Bs[brow][bcol] = bv;
        __syncthreads();
#pragma unroll
        for (int k = 0; k < 8; k++) {
            float ra[8], rb[8];
            *(float4*)&ra[0] = *(const float4*)&As[k][ty * 8];
            *(float4*)&ra[4] = *(const float4*)&As[k][ty * 8 + 4];
            *(float4*)&rb[0] = *(const float4*)&Bs[k][tx * 8];
            *(float4*)&rb[4] = *(const float4*)&Bs[k][tx * 8 + 4];
#pragma unroll
            for (int i = 0; i < 8; i++)
#pragma unroll
                for (int j = 0; j < 8; j++) acc[i][j] = fmaf(ra[i], rb[j], acc[i][j]);
        }
        __syncthreads();
    }

#pragma unroll
    for (int i = 0; i < 8; i++) {
        const int m = m0 + ty * 8 + i;
#pragma unroll
        for (int j = 0; j < 8; j++) {
            const int n = n0 + tx * 8 + j;
            out[(size_t)m * Cc + n] = acc[i][j] + bp[n];
        }
    }
}

// ---------------------------------------------------------------------------
extern "C" void kernel_launch(void* const* d_in, const int* in_sizes, int n_in,
                              void* d_out, int out_size)
{
    const float* x     = (const float*)d_in[0];  // [B,N,C]
    const float* im    = (const float*)d_in[1];  // [B,H,N,N]
    const float* mask  = (const float*)d_in[2];  // [B,1,N,N]
    const float* Wqkv  = (const float*)d_in[3];  // [C,3C]
    const float* bqkv  = (const float*)d_in[4];  // [3C]
    const float* Wproj = (const float*)d_in[5];  // [C,C]
    const float* bproj = (const float*)d_in[6];  // [C]

    float* out  = (float*)d_out;                 // [B,N,C]
    float* attn = out + OUT_ELEMS;               // [B,H,N,N]

    (void)in_sizes; (void)n_in; (void)out_size;

    qkv_gemm<<<dim3(NQKV / 128, M1 / 128), 256>>>(x, Wqkv, bqkv);
    qk_logits<<<dim3(Nn / 64, Nn / 64, BH), 256>>>(im, mask, attn);
    softmax_rows<<<(unsigned)(BH * Nn), 256>>>(attn);
    av_gemm<<<dim3(Nn / 64, BH), 256>>>(attn);
    proj_gemm<<<dim3(Cc / 128, M1 / 128), 256>>>(Wproj, bproj, out);
}